// round 6
// baseline (speedup 1.0000x reference)
#include <cuda_runtime.h>
#include <math_constants.h>

namespace {

constexpr int TOKENS   = 16384;
constexpr int NEXP     = 64;
constexpr int KDIM     = 2048;
constexpr int K_TOP    = 6;
constexpr int TILE_M   = 32;        // tokens per block
constexpr int KC       = 16;        // k-chunk
constexpr int NCH      = KDIM / KC; // 128 chunks
constexpr int NTHREADS = 128;
constexpr int XROW     = 36;        // xs row stride (TILE_M + 4)
constexpr int WROW     = 132;       // ws row stride (2*NEXP + 4), duplicated
constexpr int LROW     = 34;        // logitsT row stride (TILE_M + 2), even
constexpr float FP32_MIN_NORMAL = 1.17549435e-38f;  // 2^-126

struct __align__(16) Smem {
  union {
    struct {
      float xs[2][KC][XROW];   // [buf][k][token]      (k-major)
      float ws[2][KC][WROW];   // [buf][k][2*expert]   (duplicated {w,w})
    } mm;
    float logitsT[NEXP][LROW]; // [expert][token]
  };
};

__device__ __forceinline__ void fma2(unsigned long long& d,
                                     unsigned long long a,
                                     unsigned long long b) {
  // packed fp32x2 fused MAC: per-lane chains identical to scalar
  // sequential-k FFMA.
  asm("fma.rn.f32x2 %0, %1, %2, %0;" : "+l"(d) : "l"(a), "l"(b));
}

__device__ __forceinline__ unsigned long long pack2(float a, float b) {
  float2 t = make_float2(a, b);
  return *reinterpret_cast<unsigned long long*>(&t);
}

}  // namespace

__global__ void __launch_bounds__(NTHREADS, 4)
gate_kernel(const float* __restrict__ x, const float* __restrict__ w,
            float* __restrict__ outw, float* __restrict__ outi)
{
  __shared__ Smem sm;

  const int tid = threadIdx.x;
  const int tg  = tid & 7;     // token group : tokens tg*4 .. +3
  const int eg  = tid >> 3;    // expert group: experts eg*4 .. +3 (4 per warp)
  const int tile0 = blockIdx.x * TILE_M;

  const float4* __restrict__ x4 = reinterpret_cast<const float4*>(x);
  const float4* __restrict__ w4 = reinterpret_cast<const float4*>(w);
  const int rowF4 = KDIM / 4;  // 512 float4 per row

  // ---- global-load indexing ------------------------------------------------
  // x: TILE_M*KC = 512 floats = 128 float4 per chunk -> 1 per thread
  // w: NEXP*KC  = 1024 floats = 256 float4 per chunk -> 2 per thread
  const int xtok = tid >> 2, xk4 = tid & 3;
  const long xix = (long)(tile0 + xtok) * rowF4 + xk4;

  int wexp[2], wk4[2];
  long wix[2];
#pragma unroll
  for (int i = 0; i < 2; ++i) {
    const int f = tid + i * NTHREADS;
    wexp[i] = f >> 2;
    wk4[i]  = f & 3;
    wix[i]  = (long)wexp[i] * rowF4 + wk4[i];
  }

  float4 xst, wst[2];

  // ---- prologue: chunk 0 -> buf 0 -----------------------------------------
  xst = x4[xix];
  wst[0] = w4[wix[0]];
  wst[1] = w4[wix[1]];

  sm.mm.xs[0][xk4 * 4 + 0][xtok] = xst.x;
  sm.mm.xs[0][xk4 * 4 + 1][xtok] = xst.y;
  sm.mm.xs[0][xk4 * 4 + 2][xtok] = xst.z;
  sm.mm.xs[0][xk4 * 4 + 3][xtok] = xst.w;
#pragma unroll
  for (int i = 0; i < 2; ++i) {
    *reinterpret_cast<float2*>(&sm.mm.ws[0][wk4[i] * 4 + 0][2 * wexp[i]]) =
        make_float2(wst[i].x, wst[i].x);
    *reinterpret_cast<float2*>(&sm.mm.ws[0][wk4[i] * 4 + 1][2 * wexp[i]]) =
        make_float2(wst[i].y, wst[i].y);
    *reinterpret_cast<float2*>(&sm.mm.ws[0][wk4[i] * 4 + 2][2 * wexp[i]]) =
        make_float2(wst[i].z, wst[i].z);
    *reinterpret_cast<float2*>(&sm.mm.ws[0][wk4[i] * 4 + 3][2 * wexp[i]]) =
        make_float2(wst[i].w, wst[i].w);
  }
  __syncthreads();

  // ---- accumulators: 4 experts x 2 token-pairs, each f32x2 -----------------
  unsigned long long acc[4][2];
#pragma unroll
  for (int e = 0; e < 4; ++e)
#pragma unroll
    for (int p = 0; p < 2; ++p) acc[e][p] = 0ULL;

  // ---- mainloop ------------------------------------------------------------
  for (int c = 0; c < NCH; ++c) {
    const int buf = c & 1;

    if (c + 1 < NCH) {
      const long off = (long)(c + 1) * (KC / 4);
      xst = x4[xix + off];
      wst[0] = w4[wix[0] + off];
      wst[1] = w4[wix[1] + off];
    }

#pragma unroll
    for (int kk = 0; kk < KC; ++kk) {
      // x: 4 tokens via one LDS.128 (8 distinct 16B lines/warp = 1 phase)
      const float4 xq = *reinterpret_cast<const float4*>(
          &sm.mm.xs[buf][kk][tg * 4]);
      unsigned long long xp[2];
      xp[0] = pack2(xq.x, xq.y);
      xp[1] = pack2(xq.z, xq.w);

      // w: 4 duplicated experts via two LDS.128 (4 distinct lines/warp)
      const float4 wv0 = *reinterpret_cast<const float4*>(
          &sm.mm.ws[buf][kk][eg * 8 + 0]);
      const float4 wv1 = *reinterpret_cast<const float4*>(
          &sm.mm.ws[buf][kk][eg * 8 + 4]);
      unsigned long long wd[4];
      wd[0] = pack2(wv0.x, wv0.y);  // expert eg*4+0 duplicated
      wd[1] = pack2(wv0.z, wv0.w);  // expert eg*4+1
      wd[2] = pack2(wv1.x, wv1.y);
      wd[3] = pack2(wv1.z, wv1.w);

#pragma unroll
      for (int e = 0; e < 4; ++e)
#pragma unroll
        for (int p = 0; p < 2; ++p)
          fma2(acc[e][p], wd[e], xp[p]);
    }

    if (c + 1 < NCH) {
      const int nb = buf ^ 1;
      sm.mm.xs[nb][xk4 * 4 + 0][xtok] = xst.x;
      sm.mm.xs[nb][xk4 * 4 + 1][xtok] = xst.y;
      sm.mm.xs[nb][xk4 * 4 + 2][xtok] = xst.z;
      sm.mm.xs[nb][xk4 * 4 + 3][xtok] = xst.w;
#pragma unroll
      for (int i = 0; i < 2; ++i) {
        *reinterpret_cast<float2*>(&sm.mm.ws[nb][wk4[i] * 4 + 0][2 * wexp[i]]) =
            make_float2(wst[i].x, wst[i].x);
        *reinterpret_cast<float2*>(&sm.mm.ws[nb][wk4[i] * 4 + 1][2 * wexp[i]]) =
            make_float2(wst[i].y, wst[i].y);
        *reinterpret_cast<float2*>(&sm.mm.ws[nb][wk4[i] * 4 + 2][2 * wexp[i]]) =
            make_float2(wst[i].z, wst[i].z);
        *reinterpret_cast<float2*>(&sm.mm.ws[nb][wk4[i] * 4 + 3][2 * wexp[i]]) =
            make_float2(wst[i].w, wst[i].w);
      }
    }
    __syncthreads();
  }

  // ---- epilogue: logits -> smem (transposed [expert][token]) ---------------
#pragma unroll
  for (int e = 0; e < 4; ++e)
#pragma unroll
    for (int p = 0; p < 2; ++p) {
      const float2 v = *reinterpret_cast<float2*>(&acc[e][p]);
      *reinterpret_cast<float2*>(
          &sm.logitsT[eg * 4 + e][tg * 4 + 2 * p]) = v;
    }
  __syncthreads();

  // ---- per-token softmax (FTZ like XLA:GPU) + stable top-6 -----------------
  if (tid < TILE_M) {
    const int tok = tid;

    float mx = -CUDART_INF_F;
#pragma unroll 8
    for (int e = 0; e < NEXP; ++e) mx = fmaxf(mx, sm.logitsT[e][tok]);

    // cache exp values in smem (column-private) while summing
    float sum = 0.0f;
#pragma unroll 8
    for (int e = 0; e < NEXP; ++e) {
      const float p = expf(sm.logitsT[e][tok] - mx);
      sm.logitsT[e][tok] = p;
      sum += p;
    }

    float bv[K_TOP];
    int   bi[K_TOP];
#pragma unroll
    for (int j = 0; j < K_TOP; ++j) { bv[j] = -CUDART_INF_F; bi[j] = 0; }

    for (int e = 0; e < NEXP; ++e) {
      float s = sm.logitsT[e][tok] / sum;
      // XLA:GPU softmax is FTZ: subnormal scores become exactly 0.0 and
      // top_k tie-breaks among the zeros by lowest index. Replicate.
      if (s < FP32_MIN_NORMAL) s = 0.0f;
      if (s > bv[K_TOP - 1]) {
        bv[K_TOP - 1] = s;
        bi[K_TOP - 1] = e;
        // strict '>' keeps lowest-index-first ordering among equal scores
#pragma unroll
        for (int j = K_TOP - 1; j > 0; --j) {
          if (bv[j] > bv[j - 1]) {
            const float tv = bv[j]; bv[j] = bv[j - 1]; bv[j - 1] = tv;
            const int   ti = bi[j]; bi[j] = bi[j - 1]; bi[j - 1] = ti;
          }
        }
      }
    }

    const long gt = tile0 + tok;
#pragma unroll
    for (int j = 0; j < K_TOP; ++j) {
      outw[gt * K_TOP + j] = bv[j];
      outi[gt * K_TOP + j] = (float)bi[j];
    }
  }
}

extern "C" void kernel_launch(void* const* d_in, const int* in_sizes, int n_in,
                              void* d_out, int out_size) {
  const float* a = (const float*)d_in[0];
  const float* b = (const float*)d_in[1];
  const float* x = a;
  const float* w = b;
  if (n_in >= 2 && in_sizes[0] == NEXP * KDIM && in_sizes[1] == TOKENS * KDIM) {
    x = b; w = a;
  }

  float* out  = (float*)d_out;
  float* outw = out;                         // weights [16384, 6]
  float* outi = out + (long)TOKENS * K_TOP;  // indices (as float) [16384, 6]

  gate_kernel<<<TOKENS / TILE_M, NTHREADS>>>(x, w, outw, outi);
}

// round 7
// speedup vs baseline: 1.7961x; 1.7961x over previous
#include <cuda_runtime.h>
#include <math_constants.h>

namespace {

constexpr int TOKENS   = 16384;
constexpr int NEXP     = 64;
constexpr int KDIM     = 2048;
constexpr int K_TOP    = 6;
constexpr int TILE_M   = 64;        // tokens per block
constexpr int KC       = 16;        // k-chunk
constexpr int NCH      = KDIM / KC; // 128 chunks
constexpr int NTHREADS = 128;
constexpr int XROW     = 68;        // xs row stride (TILE_M + 4)
constexpr int WROW     = 132;       // ws row stride (2*NEXP + 4), duplicated
constexpr int LROW     = 66;        // logitsT row stride (TILE_M + 2)
constexpr float FP32_MIN_NORMAL = 1.17549435e-38f;  // 2^-126

struct __align__(16) Smem {
  union {
    struct {
      float xs[2][KC][XROW];   // [buf][k][token]      (k-major)
      float ws[2][KC][WROW];   // [buf][k][2*expert]   (duplicated {w,w})
    } mm;
    float logitsT[NEXP][LROW]; // [expert][token]
  };
};

__device__ __forceinline__ void fma2(unsigned long long& d,
                                     unsigned long long a,
                                     unsigned long long b) {
  // packed fp32x2 fused MAC: per-lane chains identical to scalar
  // sequential-k FFMA.
  asm("fma.rn.f32x2 %0, %1, %2, %0;" : "+l"(d) : "l"(a), "l"(b));
}

__device__ __forceinline__ unsigned long long pack2(float a, float b) {
  float2 t = make_float2(a, b);
  return *reinterpret_cast<unsigned long long*>(&t);
}

}  // namespace

__global__ void __launch_bounds__(NTHREADS, 2)
gate_kernel(const float* __restrict__ x, const float* __restrict__ w,
            float* __restrict__ outw, float* __restrict__ outi)
{
  __shared__ Smem sm;

  const int tid = threadIdx.x;
  const int tg  = tid & 7;     // tokens tg*4..+3 and 32+tg*4..+3 (8 per thread)
  const int eg  = tid >> 3;    // experts eg*4 .. +3 (16 groups)
  const int tile0 = blockIdx.x * TILE_M;

  const float4* __restrict__ x4 = reinterpret_cast<const float4*>(x);
  const float4* __restrict__ w4 = reinterpret_cast<const float4*>(w);
  const int rowF4 = KDIM / 4;  // 512 float4 per row

  // ---- global-load indexing ------------------------------------------------
  // x: TILE_M*KC = 1024 floats = 256 float4 per chunk -> 2 per thread
  //    token-per-lane mapping: tok = f&63, k4 = f>>6  (STS conflict-free)
  // w: NEXP*KC   = 1024 floats = 256 float4 per chunk -> 2 per thread
  int xtok[2], xk4[2], wexp[2], wk4[2];
  long xix[2], wix[2];
#pragma unroll
  for (int i = 0; i < 2; ++i) {
    const int f = tid + i * NTHREADS;
    xtok[i] = f & 63;
    xk4[i]  = f >> 6;
    xix[i]  = (long)(tile0 + xtok[i]) * rowF4 + xk4[i];
    wexp[i] = f & 63;
    wk4[i]  = f >> 6;
    wix[i]  = (long)wexp[i] * rowF4 + wk4[i];
  }

  float4 xst[2], wst[2];

  // ---- prologue: chunk 0 -> buf 0 -----------------------------------------
#pragma unroll
  for (int i = 0; i < 2; ++i) { xst[i] = x4[xix[i]]; wst[i] = w4[wix[i]]; }

#pragma unroll
  for (int i = 0; i < 2; ++i) {
    sm.mm.xs[0][xk4[i] * 4 + 0][xtok[i]] = xst[i].x;
    sm.mm.xs[0][xk4[i] * 4 + 1][xtok[i]] = xst[i].y;
    sm.mm.xs[0][xk4[i] * 4 + 2][xtok[i]] = xst[i].z;
    sm.mm.xs[0][xk4[i] * 4 + 3][xtok[i]] = xst[i].w;
    *reinterpret_cast<float2*>(&sm.mm.ws[0][wk4[i] * 4 + 0][2 * wexp[i]]) =
        make_float2(wst[i].x, wst[i].x);
    *reinterpret_cast<float2*>(&sm.mm.ws[0][wk4[i] * 4 + 1][2 * wexp[i]]) =
        make_float2(wst[i].y, wst[i].y);
    *reinterpret_cast<float2*>(&sm.mm.ws[0][wk4[i] * 4 + 2][2 * wexp[i]]) =
        make_float2(wst[i].z, wst[i].z);
    *reinterpret_cast<float2*>(&sm.mm.ws[0][wk4[i] * 4 + 3][2 * wexp[i]]) =
        make_float2(wst[i].w, wst[i].w);
  }
  __syncthreads();

  // ---- accumulators: 4 experts x 4 token-pairs, each f32x2 -----------------
  unsigned long long acc[4][4];
#pragma unroll
  for (int e = 0; e < 4; ++e)
#pragma unroll
    for (int p = 0; p < 4; ++p) acc[e][p] = 0ULL;

  // ---- mainloop ------------------------------------------------------------
  for (int c = 0; c < NCH; ++c) {
    const int buf = c & 1;

    if (c + 1 < NCH) {
      const long off = (long)(c + 1) * (KC / 4);
#pragma unroll
      for (int i = 0; i < 2; ++i) {
        xst[i] = x4[xix[i] + off];
        wst[i] = w4[wix[i] + off];
      }
    }

#pragma unroll
    for (int kk = 0; kk < KC; ++kk) {
      // x: 8 tokens as two LDS.128; tg*4 (16B stride across 8 lanes) is
      // conflict-free per 8-lane phase
      const float4 xq0 = *reinterpret_cast<const float4*>(
          &sm.mm.xs[buf][kk][tg * 4]);
      const float4 xq1 = *reinterpret_cast<const float4*>(
          &sm.mm.xs[buf][kk][32 + tg * 4]);
      unsigned long long xp[4];
      xp[0] = pack2(xq0.x, xq0.y);
      xp[1] = pack2(xq0.z, xq0.w);
      xp[2] = pack2(xq1.x, xq1.y);
      xp[3] = pack2(xq1.z, xq1.w);

      // w: 4 duplicated experts via two LDS.128; 8 consecutive lanes share
      // eg => full broadcast within each phase
      const float4 wv0 = *reinterpret_cast<const float4*>(
          &sm.mm.ws[buf][kk][eg * 8 + 0]);
      const float4 wv1 = *reinterpret_cast<const float4*>(
          &sm.mm.ws[buf][kk][eg * 8 + 4]);
      unsigned long long wd[4];
      wd[0] = pack2(wv0.x, wv0.y);  // expert eg*4+0 duplicated
      wd[1] = pack2(wv0.z, wv0.w);  // expert eg*4+1
      wd[2] = pack2(wv1.x, wv1.y);
      wd[3] = pack2(wv1.z, wv1.w);

#pragma unroll
      for (int e = 0; e < 4; ++e)
#pragma unroll
        for (int p = 0; p < 4; ++p)
          fma2(acc[e][p], wd[e], xp[p]);
    }

    if (c + 1 < NCH) {
      const int nb = buf ^ 1;
#pragma unroll
      for (int i = 0; i < 2; ++i) {
        sm.mm.xs[nb][xk4[i] * 4 + 0][xtok[i]] = xst[i].x;
        sm.mm.xs[nb][xk4[i] * 4 + 1][xtok[i]] = xst[i].y;
        sm.mm.xs[nb][xk4[i] * 4 + 2][xtok[i]] = xst[i].z;
        sm.mm.xs[nb][xk4[i] * 4 + 3][xtok[i]] = xst[i].w;
        *reinterpret_cast<float2*>(&sm.mm.ws[nb][wk4[i] * 4 + 0][2 * wexp[i]]) =
            make_float2(wst[i].x, wst[i].x);
        *reinterpret_cast<float2*>(&sm.mm.ws[nb][wk4[i] * 4 + 1][2 * wexp[i]]) =
            make_float2(wst[i].y, wst[i].y);
        *reinterpret_cast<float2*>(&sm.mm.ws[nb][wk4[i] * 4 + 2][2 * wexp[i]]) =
            make_float2(wst[i].z, wst[i].z);
        *reinterpret_cast<float2*>(&sm.mm.ws[nb][wk4[i] * 4 + 3][2 * wexp[i]]) =
            make_float2(wst[i].w, wst[i].w);
      }
    }
    __syncthreads();
  }

  // ---- epilogue: logits -> smem (transposed [expert][token]) ---------------
#pragma unroll
  for (int e = 0; e < 4; ++e)
#pragma unroll
    for (int p = 0; p < 4; ++p) {
      const float2 v = *reinterpret_cast<float2*>(&acc[e][p]);
      const int tokbase = ((p & 2) ? 32 : 0) + tg * 4 + (p & 1) * 2;
      *reinterpret_cast<float2*>(&sm.logitsT[eg * 4 + e][tokbase]) = v;
    }
  __syncthreads();

  // ---- per-token softmax (FTZ like XLA:GPU) + stable top-6 -----------------
  if (tid < TILE_M) {
    const int tok = tid;

    float mx = -CUDART_INF_F;
#pragma unroll 8
    for (int e = 0; e < NEXP; ++e) mx = fmaxf(mx, sm.logitsT[e][tok]);

    // cache exp values in smem (column-private) while summing
    float sum = 0.0f;
#pragma unroll 8
    for (int e = 0; e < NEXP; ++e) {
      const float p = expf(sm.logitsT[e][tok] - mx);
      sm.logitsT[e][tok] = p;
      sum += p;
    }

    float bv[K_TOP];
    int   bi[K_TOP];
#pragma unroll
    for (int j = 0; j < K_TOP; ++j) { bv[j] = -CUDART_INF_F; bi[j] = 0; }

    for (int e = 0; e < NEXP; ++e) {
      float s = sm.logitsT[e][tok] / sum;
      // XLA:GPU softmax is FTZ: subnormal scores become exactly 0.0 and
      // top_k tie-breaks among the zeros by lowest index. Replicate.
      if (s < FP32_MIN_NORMAL) s = 0.0f;
      if (s > bv[K_TOP - 1]) {
        bv[K_TOP - 1] = s;
        bi[K_TOP - 1] = e;
        // strict '>' keeps lowest-index-first ordering among equal scores
#pragma unroll
        for (int j = K_TOP - 1; j > 0; --j) {
          if (bv[j] > bv[j - 1]) {
            const float tv = bv[j]; bv[j] = bv[j - 1]; bv[j - 1] = tv;
            const int   ti = bi[j]; bi[j] = bi[j - 1]; bi[j - 1] = ti;
          }
        }
      }
    }

    const long gt = tile0 + tok;
#pragma unroll
    for (int j = 0; j < K_TOP; ++j) {
      outw[gt * K_TOP + j] = bv[j];
      outi[gt * K_TOP + j] = (float)bi[j];
    }
  }
}

extern "C" void kernel_launch(void* const* d_in, const int* in_sizes, int n_in,
                              void* d_out, int out_size) {
  const float* a = (const float*)d_in[0];
  const float* b = (const float*)d_in[1];
  const float* x = a;
  const float* w = b;
  if (n_in >= 2 && in_sizes[0] == NEXP * KDIM && in_sizes[1] == TOKENS * KDIM) {
    x = b; w = a;
  }

  float* out  = (float*)d_out;
  float* outw = out;                         // weights [16384, 6]
  float* outi = out + (long)TOKENS * K_TOP;  // indices (as float) [16384, 6]

  gate_kernel<<<TOKENS / TILE_M, NTHREADS>>>(x, w, outw, outi);
}